// round 1
// baseline (speedup 1.0000x reference)
#include <cuda_runtime.h>
#include <cuda_bf16.h>
#include <math.h>

// Problem constants
#define T_LEN 1024
#define K_LEN 1024
#define H_DIM 256
#define E_DIM 64
#define TOPIC 100
#define EXLEN 768
#define GRU_IN 201   // 2*TOPIC + 1
#define TOPK 64

// ---------------- device scratch (no allocations allowed) ----------------
__device__ float g_v[TOPIC];
__device__ float g_kn[E_DIM];
__device__ float g_beta[TOPK];
__device__ int   g_topidx[TOPK];
__device__ float g_alpha[K_LEN];
__device__ float g_u[3 * H_DIM];          // W_ih @ x  (768)
__device__ float g_hkp[H_DIM];            // alpha @ attn_h  (256)
__device__ float g_gh[K_LEN * 3 * H_DIM]; // h0 @ W_hh^T  (1024 x 768)

// ---------------- Kernel A: v = W_resize@ex_e + b ; kn = Wk@co_e + bk ----
__global__ void k_embed(const float* __restrict__ W_resize,
                        const float* __restrict__ b_resize,
                        const float* __restrict__ ex_e,
                        const float* __restrict__ Wk,
                        const float* __restrict__ bk,
                        const float* __restrict__ co_e) {
    int warp = threadIdx.x >> 5, lane = threadIdx.x & 31;
    // v: 100 rows, dot length 768
    for (int row = warp; row < TOPIC; row += 8) {
        const float* wr = W_resize + row * EXLEN;
        float p = 0.f;
        for (int i = lane; i < EXLEN; i += 32) p += wr[i] * ex_e[i];
        #pragma unroll
        for (int o = 16; o; o >>= 1) p += __shfl_xor_sync(0xffffffffu, p, o);
        if (lane == 0) g_v[row] = p + b_resize[row];
    }
    // kn: 64 rows, dot length 1024
    for (int row = warp; row < E_DIM; row += 8) {
        const float* wr = Wk + row * K_LEN;
        float p = 0.f;
        for (int i = lane; i < K_LEN; i += 32) p += wr[i] * co_e[i];
        #pragma unroll
        for (int o = 16; o; o >>= 1) p += __shfl_xor_sync(0xffffffffu, p, o);
        if (lane == 0) g_kn[row] = p + bk[row];
    }
}

// ---------------- Kernel B: beta_all, top-k softmax, alpha softmax, u ----
__global__ void k_select(const float* __restrict__ vs,
                         const float* __restrict__ km,
                         const float* __restrict__ s_ptr,
                         const float* __restrict__ W_ih) {
    __shared__ float sv[TOPIC];
    __shared__ float skn[E_DIM];
    __shared__ float sval[T_LEN];
    __shared__ int   sidx[T_LEN];
    __shared__ float sred[T_LEN];
    __shared__ float sx[GRU_IN + 7];

    int tid = threadIdx.x, warp = tid >> 5, lane = tid & 31;

    if (tid < TOPIC) sv[tid] = g_v[tid];
    if (tid < E_DIM) skn[tid] = g_kn[tid];
    if (tid < H_DIM) g_hkp[tid] = 0.f;   // zero accumulator each replay
    __syncthreads();

    // beta_all[row] = vs[row] . v  -- warp per row
    for (int row = warp; row < T_LEN; row += 32) {
        const float* vr = vs + row * TOPIC;
        float p = 0.f;
        for (int i = lane; i < TOPIC; i += 32) p += vr[i] * sv[i];
        #pragma unroll
        for (int o = 16; o; o >>= 1) p += __shfl_xor_sync(0xffffffffu, p, o);
        if (lane == 0) { sval[row] = p; sidx[row] = row; }
    }
    __syncthreads();

    // bitonic sort (descending) of 1024 (val, idx) pairs
    for (int kk = 2; kk <= T_LEN; kk <<= 1) {
        for (int j = kk >> 1; j > 0; j >>= 1) {
            int ixj = tid ^ j;
            if (ixj > tid) {
                float va = sval[tid], vb = sval[ixj];
                bool up = (tid & kk) == 0;          // descending segments
                bool sw = up ? (va < vb) : (va > vb);
                if (sw) {
                    int ia = sidx[tid];
                    sval[tid] = vb; sval[ixj] = va;
                    sidx[tid] = sidx[ixj]; sidx[ixj] = ia;
                }
            }
            __syncthreads();
        }
    }

    // softmax over top-64 values (warp 0)
    if (warp == 0) {
        float m  = sval[0];
        float e0 = __expf(sval[lane] - m);
        float e1 = __expf(sval[lane + 32] - m);
        float sm = e0 + e1;
        #pragma unroll
        for (int o = 16; o; o >>= 1) sm += __shfl_xor_sync(0xffffffffu, sm, o);
        g_beta[lane]       = e0 / sm;
        g_beta[lane + 32]  = e1 / sm;
        g_topidx[lane]      = sidx[lane];
        g_topidx[lane + 32] = sidx[lane + 32];
    }

    // alpha = softmax(km @ kn), one thread per knowledge row
    float dotv = 0.f;
    {
        const float* kr = km + tid * E_DIM;
        #pragma unroll 16
        for (int e = 0; e < E_DIM; e++) dotv += kr[e] * skn[e];
    }
    sred[tid] = dotv;
    __syncthreads();
    for (int o = 512; o; o >>= 1) {
        if (tid < o) sred[tid] = fmaxf(sred[tid], sred[tid + o]);
        __syncthreads();
    }
    float mx = sred[0];
    __syncthreads();
    float ev = __expf(dotv - mx);
    sred[tid] = ev;
    __syncthreads();
    for (int o = 512; o; o >>= 1) {
        if (tid < o) sred[tid] += sred[tid + o];
        __syncthreads();
    }
    g_alpha[tid] = ev / sred[0];

    // x = [v*mask, v*(1-mask), s];  u = W_ih @ x  (factoring alpha out of xk)
    float s = s_ptr[0];
    float mask = (s >= 0.5f) ? 1.f : 0.f;
    if (tid < TOPIC) { sx[tid] = sv[tid] * mask; sx[TOPIC + tid] = sv[tid] * (1.f - mask); }
    if (tid == 0) sx[2 * TOPIC] = s;
    __syncthreads();
    for (int row = warp; row < 3 * H_DIM; row += 32) {
        const float* wr = W_ih + row * GRU_IN;
        float p = 0.f;
        for (int i = lane; i < GRU_IN; i += 32) p += wr[i] * sx[i];
        #pragma unroll
        for (int o = 16; o; o >>= 1) p += __shfl_xor_sync(0xffffffffu, p, o);
        if (lane == 0) g_u[row] = p;
    }
}

// ------- Kernel C: hkp[hh] = sum_j beta_j * sum_kk alpha_kk * hs[idx_j,kk,hh]
// grid (64 slices, 8 row-chunks of 128), 256 threads. 67 MB streamed.
__global__ void k_gather(const float* __restrict__ hs) {
    __shared__ float  sal[128];
    __shared__ float4 sacc[256];
    int j = blockIdx.x;
    int kk0 = blockIdx.y * 128;
    int tid = threadIdx.x;
    if (tid < 128) sal[tid] = g_alpha[kk0 + tid];
    __syncthreads();

    int slice = g_topidx[j];
    const float4* base = (const float4*)hs
                       + (size_t)slice * (K_LEN * (H_DIM / 4))
                       + (size_t)kk0 * (H_DIM / 4);
    int t4 = tid & 63;    // float4 column (hh/4)
    int rg = tid >> 6;    // 0..3 row group
    float4 acc = make_float4(0.f, 0.f, 0.f, 0.f);
    #pragma unroll 8
    for (int r = rg; r < 128; r += 4) {
        float a = sal[r];
        float4 vv = base[r * (H_DIM / 4) + t4];
        acc.x += a * vv.x; acc.y += a * vv.y;
        acc.z += a * vv.z; acc.w += a * vv.w;
    }
    sacc[tid] = acc;
    __syncthreads();
    if (tid < 64) {
        float4 a0 = sacc[tid], a1 = sacc[64 + tid], a2 = sacc[128 + tid], a3 = sacc[192 + tid];
        float b = g_beta[j];
        atomicAdd(&g_hkp[tid * 4 + 0], b * (a0.x + a1.x + a2.x + a3.x));
        atomicAdd(&g_hkp[tid * 4 + 1], b * (a0.y + a1.y + a2.y + a3.y));
        atomicAdd(&g_hkp[tid * 4 + 2], b * (a0.z + a1.z + a2.z + a3.z));
        atomicAdd(&g_hkp[tid * 4 + 3], b * (a0.w + a1.w + a2.w + a3.w));
    }
}

// ------- Kernel D: g_gh[1024,768] = h0[1024,256] @ W_hh^T[256,768] ---------
// 64x64 tile, BK=16, 4x4 micro-tile per thread.
#define BM 64
#define BN 64
#define BKD 16
__global__ void k_gemm(const float* __restrict__ A,   // h0  [1024,256]
                       const float* __restrict__ B) { // W_hh [768,256]
    __shared__ float As[BKD][68];
    __shared__ float Bs[BKD][68];
    int tid = threadIdx.x;
    int m0 = blockIdx.y * BM;
    int n0 = blockIdx.x * BN;
    int tx = tid & 15, ty = tid >> 4;
    int lr = tid >> 2;           // 0..63 tile row
    int lc = (tid & 3) * 4;      // 0,4,8,12 k offset
    float c[4][4] = {};
    for (int k0 = 0; k0 < H_DIM; k0 += BKD) {
        float4 av = *(const float4*)(A + (size_t)(m0 + lr) * H_DIM + k0 + lc);
        float4 bv = *(const float4*)(B + (size_t)(n0 + lr) * H_DIM + k0 + lc);
        As[lc + 0][lr] = av.x; As[lc + 1][lr] = av.y; As[lc + 2][lr] = av.z; As[lc + 3][lr] = av.w;
        Bs[lc + 0][lr] = bv.x; Bs[lc + 1][lr] = bv.y; Bs[lc + 2][lr] = bv.z; Bs[lc + 3][lr] = bv.w;
        __syncthreads();
        #pragma unroll
        for (int kk = 0; kk < BKD; kk++) {
            float a[4], b[4];
            #pragma unroll
            for (int i = 0; i < 4; i++) a[i] = As[kk][ty * 4 + i];
            #pragma unroll
            for (int i = 0; i < 4; i++) b[i] = Bs[kk][tx * 4 + i];
            #pragma unroll
            for (int i = 0; i < 4; i++)
                #pragma unroll
                for (int jx = 0; jx < 4; jx++) c[i][jx] = fmaf(a[i], b[jx], c[i][jx]);
        }
        __syncthreads();
    }
    #pragma unroll
    for (int i = 0; i < 4; i++) {
        float4 v = make_float4(c[i][0], c[i][1], c[i][2], c[i][3]);
        *(float4*)(g_gh + (size_t)(m0 + ty * 4 + i) * (3 * H_DIM) + n0 + tx * 4) = v;
    }
}

// ------- Kernel E: GRU gates + h_new + predict_score -----------------------
__global__ void k_gru(const float* __restrict__ h0,
                      const float* __restrict__ b_ih,
                      const float* __restrict__ b_hh,
                      const float* __restrict__ W_score,
                      const float* __restrict__ b_score,
                      float* __restrict__ out) {
    int kk = blockIdx.x;
    int hh = threadIdx.x;
    float a = g_alpha[kk];
    const float* gh = g_gh + (size_t)kk * (3 * H_DIM);

    float gir = fmaf(a, g_u[hh],             b_ih[hh]);
    float giz = fmaf(a, g_u[H_DIM + hh],     b_ih[H_DIM + hh]);
    float gin = fmaf(a, g_u[2 * H_DIM + hh], b_ih[2 * H_DIM + hh]);
    float ghr = gh[hh]             + b_hh[hh];
    float ghz = gh[H_DIM + hh]     + b_hh[H_DIM + hh];
    float ghn = gh[2 * H_DIM + hh] + b_hh[2 * H_DIM + hh];

    float r = 1.f / (1.f + __expf(-(gir + ghr)));
    float z = 1.f / (1.f + __expf(-(giz + ghz)));
    float n = tanhf(gin + r * ghn);
    float h0v = h0[(size_t)kk * H_DIM + hh];
    out[1 + (size_t)kk * H_DIM + hh] = (1.f - z) * n + z * h0v;

    // predict_score = W_score . [v ; hkp] + b_score  (block 0, warp 0)
    if (kk == 0 && hh < 32) {
        float p = 0.f;
        for (int i = hh; i < TOPIC + H_DIM; i += 32) {
            float pv = (i < TOPIC) ? g_v[i] : g_hkp[i - TOPIC];
            p += W_score[i] * pv;
        }
        #pragma unroll
        for (int o = 16; o; o >>= 1) p += __shfl_xor_sync(0xffffffffu, p, o);
        if (hh == 0) out[0] = p + b_score[0];
    }
}

// ---------------------------------------------------------------------------
extern "C" void kernel_launch(void* const* d_in, const int* in_sizes, int n_in,
                              void* d_out, int out_size) {
    const float* co_e     = (const float*)d_in[0];
    const float* ex_e     = (const float*)d_in[1];
    const float* s        = (const float*)d_in[2];
    const float* h        = (const float*)d_in[3];   // [1,K,H] -> h0
    const float* vs       = (const float*)d_in[4];
    const float* hs       = (const float*)d_in[5];
    const float* W_resize = (const float*)d_in[6];
    const float* b_resize = (const float*)d_in[7];
    const float* Wk       = (const float*)d_in[8];
    const float* bk       = (const float*)d_in[9];
    const float* km       = (const float*)d_in[10];
    const float* W_score  = (const float*)d_in[11];
    const float* b_score  = (const float*)d_in[12];
    const float* W_ih     = (const float*)d_in[13];
    const float* W_hh     = (const float*)d_in[14];
    const float* b_ih     = (const float*)d_in[15];
    const float* b_hh     = (const float*)d_in[16];
    float* out = (float*)d_out;

    k_embed <<<1, 256>>>(W_resize, b_resize, ex_e, Wk, bk, co_e);
    k_select<<<1, 1024>>>(vs, km, s, W_ih);
    k_gather<<<dim3(TOPK, 8), 256>>>(hs);
    k_gemm  <<<dim3((3 * H_DIM) / BN, K_LEN / BM), 256>>>(h, W_hh);
    k_gru   <<<K_LEN, 256>>>(h, b_ih, b_hh, W_score, b_score, out);
}

// round 3
// speedup vs baseline: 3.3017x; 3.3017x over previous
#include <cuda_runtime.h>
#include <cuda_bf16.h>
#include <math.h>

#define T_LEN 1024
#define K_LEN 1024
#define H_DIM 256
#define E_DIM 64
#define TOPIC 100
#define EXLEN 768
#define GRU_IN 201   // 2*TOPIC + 1
#define TOPK 64

// ---------------- device scratch ----------------
__device__ float g_v[TOPIC];
__device__ float g_kn[E_DIM];
__device__ float g_betaall[T_LEN];
__device__ float g_adot[K_LEN];
__device__ float g_beta[TOPK];
__device__ int   g_topidx[TOPK];
__device__ float g_alpha[K_LEN];
__device__ float g_u[3 * H_DIM];
__device__ float g_hkp[H_DIM];
__device__ float g_gh[K_LEN * 3 * H_DIM];

// ---------------- K1: v = W_resize@ex_e + b ; kn = Wk@co_e + bk ----------
// grid 21 x 256 (168 warps; 164 used). Also zeros g_hkp.
__global__ void k1_embed(const float* __restrict__ W_resize,
                         const float* __restrict__ b_resize,
                         const float* __restrict__ ex_e,
                         const float* __restrict__ Wk,
                         const float* __restrict__ bk,
                         const float* __restrict__ co_e) {
    int lane = threadIdx.x & 31;
    int gw = blockIdx.x * 8 + (threadIdx.x >> 5);
    if (blockIdx.x == 0 && threadIdx.x < H_DIM) g_hkp[threadIdx.x] = 0.f;
    if (gw < TOPIC) {
        const float* wr = W_resize + gw * EXLEN;
        float p = 0.f;
        for (int i = lane; i < EXLEN; i += 32) p += wr[i] * ex_e[i];
        #pragma unroll
        for (int o = 16; o; o >>= 1) p += __shfl_xor_sync(0xffffffffu, p, o);
        if (lane == 0) g_v[gw] = p + b_resize[gw];
    } else if (gw < TOPIC + E_DIM) {
        int row = gw - TOPIC;
        const float* wr = Wk + row * K_LEN;
        float p = 0.f;
        for (int i = lane; i < K_LEN; i += 32) p += wr[i] * co_e[i];
        #pragma unroll
        for (int o = 16; o; o >>= 1) p += __shfl_xor_sync(0xffffffffu, p, o);
        if (lane == 0) g_kn[row] = p + bk[row];
    }
}

// ---------------- K2: beta_all, alpha dots, u = W_ih@x -------------------
// 2816 warps total -> grid 352 x 256.
__global__ void k2_dots(const float* __restrict__ vs,
                        const float* __restrict__ km,
                        const float* __restrict__ W_ih,
                        const float* __restrict__ s_ptr) {
    int lane = threadIdx.x & 31;
    int gw = blockIdx.x * 8 + (threadIdx.x >> 5);
    if (gw < T_LEN) {
        const float* vr = vs + gw * TOPIC;
        float p = 0.f;
        for (int i = lane; i < TOPIC; i += 32) p += vr[i] * g_v[i];
        #pragma unroll
        for (int o = 16; o; o >>= 1) p += __shfl_xor_sync(0xffffffffu, p, o);
        if (lane == 0) g_betaall[gw] = p;
    } else if (gw < 2 * T_LEN) {
        int row = gw - T_LEN;
        const float* kr = km + row * E_DIM;
        float p = 0.f;
        for (int i = lane; i < E_DIM; i += 32) p += kr[i] * g_kn[i];
        #pragma unroll
        for (int o = 16; o; o >>= 1) p += __shfl_xor_sync(0xffffffffu, p, o);
        if (lane == 0) g_adot[row] = p;
    } else if (gw < 2 * T_LEN + 3 * H_DIM) {
        int row = gw - 2 * T_LEN;
        float s = s_ptr[0];
        float mask = (s >= 0.5f) ? 1.f : 0.f;
        const float* wr = W_ih + row * GRU_IN;
        float p = 0.f;
        for (int i = lane; i < GRU_IN; i += 32) {
            float xv = (i < TOPIC) ? g_v[i] * mask
                     : (i < 2 * TOPIC) ? g_v[i - TOPIC] * (1.f - mask) : s;
            p += wr[i] * xv;
        }
        #pragma unroll
        for (int o = 16; o; o >>= 1) p += __shfl_xor_sync(0xffffffffu, p, o);
        if (lane == 0) g_u[row] = p;
    }
}

// ---------------- K3: top-k sort + both softmaxes (small serial core) ----
__global__ void k3_select() {
    __shared__ float sval[T_LEN];
    __shared__ int   sidx[T_LEN];
    __shared__ float sred[T_LEN];
    int tid = threadIdx.x, lane = tid & 31;

    sval[tid] = g_betaall[tid];
    sidx[tid] = tid;
    float dotv = g_adot[tid];
    __syncthreads();

    // bitonic sort descending
    for (int kk = 2; kk <= T_LEN; kk <<= 1) {
        for (int j = kk >> 1; j > 0; j >>= 1) {
            int ixj = tid ^ j;
            if (ixj > tid) {
                float va = sval[tid], vb = sval[ixj];
                bool up = (tid & kk) == 0;
                bool sw = up ? (va < vb) : (va > vb);
                if (sw) {
                    int ia = sidx[tid];
                    sval[tid] = vb; sval[ixj] = va;
                    sidx[tid] = sidx[ixj]; sidx[ixj] = ia;
                }
            }
            __syncthreads();
        }
    }

    if (tid < 32) {   // softmax over top-64 (warp 0)
        float m  = sval[0];
        float e0 = __expf(sval[lane] - m);
        float e1 = __expf(sval[lane + 32] - m);
        float sm = e0 + e1;
        #pragma unroll
        for (int o = 16; o; o >>= 1) sm += __shfl_xor_sync(0xffffffffu, sm, o);
        g_beta[lane]        = e0 / sm;
        g_beta[lane + 32]   = e1 / sm;
        g_topidx[lane]      = sidx[lane];
        g_topidx[lane + 32] = sidx[lane + 32];
    }

    // alpha = softmax(adot)
    sred[tid] = dotv;
    __syncthreads();
    for (int o = 512; o; o >>= 1) {
        if (tid < o) sred[tid] = fmaxf(sred[tid], sred[tid + o]);
        __syncthreads();
    }
    float mx = sred[0];
    __syncthreads();
    float ev = __expf(dotv - mx);
    sred[tid] = ev;
    __syncthreads();
    for (int o = 512; o; o >>= 1) {
        if (tid < o) sred[tid] += sred[tid + o];
        __syncthreads();
    }
    g_alpha[tid] = ev / sred[0];
}

// ---------------- K4: fused GEMM (192 blocks) + gather (512 blocks) ------
#define BM 64
#define BN 64
#define BKD 16
#define GEMM_BLOCKS 192
__global__ void k4_fused(const float* __restrict__ A,   // h0 [1024,256]
                         const float* __restrict__ B,   // W_hh [768,256]
                         const float* __restrict__ hs) {
    __shared__ union {
        struct { float As[BKD][68]; float Bs[BKD][68]; } g;
        struct { float sal[128]; float4 sacc[256]; } t;
    } sm;
    int tid = threadIdx.x;

    if (blockIdx.x < GEMM_BLOCKS) {
        // ---- GEMM path: g_gh = h0 @ W_hh^T ----
        int nblk = blockIdx.x % 12;
        int mblk = blockIdx.x / 12;
        int m0 = mblk * BM, n0 = nblk * BN;
        int tx = tid & 15, ty = tid >> 4;
        int lr = tid >> 2;
        int lc = (tid & 3) * 4;
        float c[4][4] = {};
        for (int k0 = 0; k0 < H_DIM; k0 += BKD) {
            float4 av = *(const float4*)(A + (size_t)(m0 + lr) * H_DIM + k0 + lc);
            float4 bv = *(const float4*)(B + (size_t)(n0 + lr) * H_DIM + k0 + lc);
            sm.g.As[lc + 0][lr] = av.x; sm.g.As[lc + 1][lr] = av.y;
            sm.g.As[lc + 2][lr] = av.z; sm.g.As[lc + 3][lr] = av.w;
            sm.g.Bs[lc + 0][lr] = bv.x; sm.g.Bs[lc + 1][lr] = bv.y;
            sm.g.Bs[lc + 2][lr] = bv.z; sm.g.Bs[lc + 3][lr] = bv.w;
            __syncthreads();
            #pragma unroll
            for (int kk = 0; kk < BKD; kk++) {
                float a[4], b[4];
                #pragma unroll
                for (int i = 0; i < 4; i++) a[i] = sm.g.As[kk][ty * 4 + i];
                #pragma unroll
                for (int i = 0; i < 4; i++) b[i] = sm.g.Bs[kk][tx * 4 + i];
                #pragma unroll
                for (int i = 0; i < 4; i++)
                    #pragma unroll
                    for (int jx = 0; jx < 4; jx++) c[i][jx] = fmaf(a[i], b[jx], c[i][jx]);
            }
            __syncthreads();
        }
        #pragma unroll
        for (int i = 0; i < 4; i++) {
            float4 v = make_float4(c[i][0], c[i][1], c[i][2], c[i][3]);
            *(float4*)(g_gh + (size_t)(m0 + ty * 4 + i) * (3 * H_DIM) + n0 + tx * 4) = v;
        }
    } else {
        // ---- gather path: hkp += beta_j * alpha_kk * hs[idx_j, kk, :] ----
        int g = blockIdx.x - GEMM_BLOCKS;       // 0..511
        int j = g & 63;
        int kk0 = (g >> 6) * 128;
        if (tid < 128) sm.t.sal[tid] = g_alpha[kk0 + tid];
        __syncthreads();

        int slice = g_topidx[j];
        const float4* base = (const float4*)hs
                           + (size_t)slice * (K_LEN * (H_DIM / 4))
                           + (size_t)kk0 * (H_DIM / 4);
        int t4 = tid & 63;
        int rg = tid >> 6;
        float4 acc = make_float4(0.f, 0.f, 0.f, 0.f);
        #pragma unroll 8
        for (int r = rg; r < 128; r += 4) {
            float a = sm.t.sal[r];
            float4 vv = base[r * (H_DIM / 4) + t4];
            acc.x += a * vv.x; acc.y += a * vv.y;
            acc.z += a * vv.z; acc.w += a * vv.w;
        }
        sm.t.sacc[tid] = acc;
        __syncthreads();
        if (tid < 64) {
            float4 a0 = sm.t.sacc[tid], a1 = sm.t.sacc[64 + tid];
            float4 a2 = sm.t.sacc[128 + tid], a3 = sm.t.sacc[192 + tid];
            float b = g_beta[j];
            atomicAdd(&g_hkp[tid * 4 + 0], b * (a0.x + a1.x + a2.x + a3.x));
            atomicAdd(&g_hkp[tid * 4 + 1], b * (a0.y + a1.y + a2.y + a3.y));
            atomicAdd(&g_hkp[tid * 4 + 2], b * (a0.z + a1.z + a2.z + a3.z));
            atomicAdd(&g_hkp[tid * 4 + 3], b * (a0.w + a1.w + a2.w + a3.w));
        }
    }
}

// ---------------- K5: GRU gates + h_new + predict_score ------------------
__global__ void k5_gru(const float* __restrict__ h0,
                       const float* __restrict__ b_ih,
                       const float* __restrict__ b_hh,
                       const float* __restrict__ W_score,
                       const float* __restrict__ b_score,
                       float* __restrict__ out) {
    int kk = blockIdx.x;
    int hh = threadIdx.x;
    float a = g_alpha[kk];
    const float* gh = g_gh + (size_t)kk * (3 * H_DIM);

    float gir = fmaf(a, g_u[hh],             b_ih[hh]);
    float giz = fmaf(a, g_u[H_DIM + hh],     b_ih[H_DIM + hh]);
    float gin = fmaf(a, g_u[2 * H_DIM + hh], b_ih[2 * H_DIM + hh]);
    float ghr = gh[hh]             + b_hh[hh];
    float ghz = gh[H_DIM + hh]     + b_hh[H_DIM + hh];
    float ghn = gh[2 * H_DIM + hh] + b_hh[2 * H_DIM + hh];

    float r = 1.f / (1.f + __expf(-(gir + ghr)));
    float z = 1.f / (1.f + __expf(-(giz + ghz)));
    float n = tanhf(gin + r * ghn);
    float h0v = h0[(size_t)kk * H_DIM + hh];
    out[1 + (size_t)kk * H_DIM + hh] = (1.f - z) * n + z * h0v;

    if (kk == 0 && hh < 32) {
        float p = 0.f;
        for (int i = hh; i < TOPIC + H_DIM; i += 32) {
            float pv = (i < TOPIC) ? g_v[i] : g_hkp[i - TOPIC];
            p += W_score[i] * pv;
        }
        #pragma unroll
        for (int o = 16; o; o >>= 1) p += __shfl_xor_sync(0xffffffffu, p, o);
        if (hh == 0) out[0] = p + b_score[0];
    }
}

// ---------------------------------------------------------------------------
extern "C" void kernel_launch(void* const* d_in, const int* in_sizes, int n_in,
                              void* d_out, int out_size) {
    const float* co_e     = (const float*)d_in[0];
    const float* ex_e     = (const float*)d_in[1];
    const float* s        = (const float*)d_in[2];
    const float* h        = (const float*)d_in[3];
    const float* vs       = (const float*)d_in[4];
    const float* hs       = (const float*)d_in[5];
    const float* W_resize = (const float*)d_in[6];
    const float* b_resize = (const float*)d_in[7];
    const float* Wk       = (const float*)d_in[8];
    const float* bk       = (const float*)d_in[9];
    const float* km       = (const float*)d_in[10];
    const float* W_score  = (const float*)d_in[11];
    const float* b_score  = (const float*)d_in[12];
    const float* W_ih     = (const float*)d_in[13];
    const float* W_hh     = (const float*)d_in[14];
    const float* b_ih     = (const float*)d_in[15];
    const float* b_hh     = (const float*)d_in[16];
    float* out = (float*)d_out;

    k1_embed<<<21, 256>>>(W_resize, b_resize, ex_e, Wk, bk, co_e);
    k2_dots <<<352, 256>>>(vs, km, W_ih, s);
    k3_select<<<1, 1024>>>();
    k4_fused<<<GEMM_BLOCKS + 512, 256>>>(h, W_hh, hs);
    k5_gru  <<<K_LEN, 256>>>(h, b_ih, b_hh, W_score, b_score, out);
}

// round 5
// speedup vs baseline: 4.4307x; 1.3420x over previous
#include <cuda_runtime.h>
#include <cuda_bf16.h>
#include <math.h>

#define T_LEN 1024
#define K_LEN 1024
#define H_DIM 256
#define E_DIM 64
#define TOPIC 100
#define EXLEN 768
#define GRU_IN 201   // 2*TOPIC + 1
#define TOPK 64

// ---------------- device scratch ----------------
__device__ float g_v[TOPIC];
__device__ float g_kn[E_DIM];
__device__ float g_betaall[T_LEN];
__device__ float g_adot[K_LEN];
__device__ float g_beta[TOPK];
__device__ int   g_topidx[TOPK];
__device__ float g_alpha[K_LEN];
__device__ float g_u[3 * H_DIM];
__device__ float g_hkp[H_DIM];
__device__ float g_gh[K_LEN * 3 * H_DIM];

__device__ __forceinline__ unsigned f2tf32(float f) {
    unsigned r;
    asm("cvt.rna.tf32.f32 %0, %1;" : "=r"(r) : "f"(f));
    return r;
}

// ---------------- K1: v = W_resize@ex_e + b ; kn = Wk@co_e + bk ----------
__global__ void k1_embed(const float* __restrict__ W_resize,
                         const float* __restrict__ b_resize,
                         const float* __restrict__ ex_e,
                         const float* __restrict__ Wk,
                         const float* __restrict__ bk,
                         const float* __restrict__ co_e) {
    int lane = threadIdx.x & 31;
    int gw = blockIdx.x * 8 + (threadIdx.x >> 5);
    if (blockIdx.x == 0 && threadIdx.x < H_DIM) g_hkp[threadIdx.x] = 0.f;
    if (gw < TOPIC) {
        const float* wr = W_resize + gw * EXLEN;
        float p = 0.f;
        for (int i = lane; i < EXLEN; i += 32) p += wr[i] * ex_e[i];
        #pragma unroll
        for (int o = 16; o; o >>= 1) p += __shfl_xor_sync(0xffffffffu, p, o);
        if (lane == 0) g_v[gw] = p + b_resize[gw];
    } else if (gw < TOPIC + E_DIM) {
        int row = gw - TOPIC;
        const float* wr = Wk + row * K_LEN;
        float p = 0.f;
        for (int i = lane; i < K_LEN; i += 32) p += wr[i] * co_e[i];
        #pragma unroll
        for (int o = 16; o; o >>= 1) p += __shfl_xor_sync(0xffffffffu, p, o);
        if (lane == 0) g_kn[row] = p + bk[row];
    }
}

// ---------------- K2: beta_all, alpha dots, u = W_ih@x -------------------
__global__ void k2_dots(const float* __restrict__ vs,
                        const float* __restrict__ km,
                        const float* __restrict__ W_ih,
                        const float* __restrict__ s_ptr) {
    int lane = threadIdx.x & 31;
    int gw = blockIdx.x * 8 + (threadIdx.x >> 5);
    if (gw < T_LEN) {
        const float* vr = vs + gw * TOPIC;
        float p = 0.f;
        for (int i = lane; i < TOPIC; i += 32) p += vr[i] * g_v[i];
        #pragma unroll
        for (int o = 16; o; o >>= 1) p += __shfl_xor_sync(0xffffffffu, p, o);
        if (lane == 0) g_betaall[gw] = p;
    } else if (gw < 2 * T_LEN) {
        int row = gw - T_LEN;
        const float* kr = km + row * E_DIM;
        float p = 0.f;
        for (int i = lane; i < E_DIM; i += 32) p += kr[i] * g_kn[i];
        #pragma unroll
        for (int o = 16; o; o >>= 1) p += __shfl_xor_sync(0xffffffffu, p, o);
        if (lane == 0) g_adot[row] = p;
    } else if (gw < 2 * T_LEN + 3 * H_DIM) {
        int row = gw - 2 * T_LEN;
        float s = s_ptr[0];
        float mask = (s >= 0.5f) ? 1.f : 0.f;
        const float* wr = W_ih + row * GRU_IN;
        float p = 0.f;
        for (int i = lane; i < GRU_IN; i += 32) {
            float xv = (i < TOPIC) ? g_v[i] * mask
                     : (i < 2 * TOPIC) ? g_v[i - TOPIC] * (1.f - mask) : s;
            p += wr[i] * xv;
        }
        #pragma unroll
        for (int o = 16; o; o >>= 1) p += __shfl_xor_sync(0xffffffffu, p, o);
        if (lane == 0) g_u[row] = p;
    }
}

// ---------------- K3: hybrid bitonic top-k + softmaxes -------------------
__global__ void k3_select() {
    __shared__ unsigned long long skey[T_LEN];
    __shared__ float sv2[TOPK];
    __shared__ int   si2[TOPK];
    __shared__ float sred[32];
    int tid = threadIdx.x, lane = tid & 31, wid = tid >> 5;

    float bv = g_betaall[tid];
    unsigned u = __float_as_uint(bv);
    u = (u & 0x80000000u) ? ~u : (u | 0x80000000u);
    unsigned long long key = ((unsigned long long)u << 32) | (unsigned)tid;

    // bitonic sort descending; intra-warp rounds via shfl, cross-warp via smem
    for (int k = 2; k <= T_LEN; k <<= 1) {
        for (int j = k >> 1; j > 0; j >>= 1) {
            bool keepmax = (((tid & k) == 0) == ((tid & j) == 0));
            unsigned long long p;
            if (j >= 32) {
                skey[tid] = key;
                __syncthreads();
                p = skey[tid ^ j];
                __syncthreads();
            } else {
                p = __shfl_xor_sync(0xffffffffu, key, j);
            }
            unsigned long long hi = (key > p) ? key : p;
            unsigned long long lo = (key > p) ? p : key;
            key = keepmax ? hi : lo;
        }
    }

    if (tid < TOPK) {
        unsigned su = (unsigned)(key >> 32);
        float val = __uint_as_float((su & 0x80000000u) ? (su ^ 0x80000000u) : ~su);
        sv2[tid] = val;
        si2[tid] = (int)(key & 0xffffffffu);
    }
    __syncthreads();

    if (tid < 32) {   // softmax over top-64
        float m  = sv2[0];
        float e0 = __expf(sv2[lane] - m);
        float e1 = __expf(sv2[lane + 32] - m);
        float sm = e0 + e1;
        #pragma unroll
        for (int o = 16; o; o >>= 1) sm += __shfl_xor_sync(0xffffffffu, sm, o);
        g_beta[lane]        = e0 / sm;
        g_beta[lane + 32]   = e1 / sm;
        g_topidx[lane]      = si2[lane];
        g_topidx[lane + 32] = si2[lane + 32];
    }

    // alpha = softmax(g_adot) -- two-level shfl reductions
    float dv = g_adot[tid];
    float wmax = dv;
    #pragma unroll
    for (int o = 16; o; o >>= 1) wmax = fmaxf(wmax, __shfl_xor_sync(0xffffffffu, wmax, o));
    if (lane == 0) sred[wid] = wmax;
    __syncthreads();
    if (tid < 32) {
        float x = sred[lane];
        #pragma unroll
        for (int o = 16; o; o >>= 1) x = fmaxf(x, __shfl_xor_sync(0xffffffffu, x, o));
        if (lane == 0) sred[0] = x;
    }
    __syncthreads();
    float mx = sred[0];
    __syncthreads();
    float ev = __expf(dv - mx);
    float ws = ev;
    #pragma unroll
    for (int o = 16; o; o >>= 1) ws += __shfl_xor_sync(0xffffffffu, ws, o);
    if (lane == 0) sred[wid] = ws;
    __syncthreads();
    if (tid < 32) {
        float x = sred[lane];
        #pragma unroll
        for (int o = 16; o; o >>= 1) x += __shfl_xor_sync(0xffffffffu, x, o);
        if (lane == 0) sred[0] = x;
    }
    __syncthreads();
    g_alpha[tid] = ev / sred[0];
}

// ---------------- K4: fused tf32-MMA GEMM (96 blocks) + gather (512) -----
#define GBM 128
#define GBN 64
#define GEMM_BLOCKS 96

__device__ __forceinline__ void mma_tf32(float* c, const unsigned* a, const unsigned* b) {
    asm volatile(
        "mma.sync.aligned.m16n8k8.row.col.f32.tf32.tf32.f32 "
        "{%0,%1,%2,%3}, {%4,%5,%6,%7}, {%8,%9}, {%0,%1,%2,%3};\n"
        : "+f"(c[0]), "+f"(c[1]), "+f"(c[2]), "+f"(c[3])
        : "r"(a[0]), "r"(a[1]), "r"(a[2]), "r"(a[3]), "r"(b[0]), "r"(b[1]));
}

__global__ void k4_fused(const float* __restrict__ A,   // h0 [1024,256]
                         const float* __restrict__ B,   // W_hh [768,256]
                         const float* __restrict__ hs) {
    __shared__ union {
        struct { unsigned As[GBM][36]; unsigned Bs[GBN][36]; } g;
        struct { float sal[128]; float4 sacc[256]; } t;
    } sm;
    int tid = threadIdx.x;

    if (blockIdx.x < GEMM_BLOCKS) {
        // ---- tf32 MMA GEMM: g_gh = h0 @ W_hh^T ----
        int nblk = blockIdx.x % 12;
        int mblk = blockIdx.x / 12;
        int m0 = mblk * GBM, n0 = nblk * GBN;
        int lane = tid & 31, wid = tid >> 5;
        int wm = (wid & 3) * 32, wn = (wid >> 2) * 32;
        int g = lane >> 2, tg = lane & 3;
        int lr = tid >> 3;            // 0..31
        int lc4 = (tid & 7) * 4;      // 0,4..28

        float c[2][4][4];
        #pragma unroll
        for (int mt = 0; mt < 2; mt++)
            #pragma unroll
            for (int nt = 0; nt < 4; nt++)
                #pragma unroll
                for (int i = 0; i < 4; i++) c[mt][nt][i] = 0.f;

        for (int kt = 0; kt < H_DIM; kt += 32) {
            float4 a4[4], b4[2];
            #pragma unroll
            for (int i = 0; i < 4; i++)
                a4[i] = *(const float4*)(A + (size_t)(m0 + lr + 32 * i) * H_DIM + kt + lc4);
            #pragma unroll
            for (int i = 0; i < 2; i++)
                b4[i] = *(const float4*)(B + (size_t)(n0 + lr + 32 * i) * H_DIM + kt + lc4);
            __syncthreads();
            #pragma unroll
            for (int i = 0; i < 4; i++) {
                sm.g.As[lr + 32 * i][lc4 + 0] = f2tf32(a4[i].x);
                sm.g.As[lr + 32 * i][lc4 + 1] = f2tf32(a4[i].y);
                sm.g.As[lr + 32 * i][lc4 + 2] = f2tf32(a4[i].z);
                sm.g.As[lr + 32 * i][lc4 + 3] = f2tf32(a4[i].w);
            }
            #pragma unroll
            for (int i = 0; i < 2; i++) {
                sm.g.Bs[lr + 32 * i][lc4 + 0] = f2tf32(b4[i].x);
                sm.g.Bs[lr + 32 * i][lc4 + 1] = f2tf32(b4[i].y);
                sm.g.Bs[lr + 32 * i][lc4 + 2] = f2tf32(b4[i].z);
                sm.g.Bs[lr + 32 * i][lc4 + 3] = f2tf32(b4[i].w);
            }
            __syncthreads();
            #pragma unroll
            for (int ks = 0; ks < 32; ks += 8) {
                unsigned afr[2][4], bfr[4][2];
                #pragma unroll
                for (int mt = 0; mt < 2; mt++) {
                    int r0 = wm + mt * 16 + g;
                    afr[mt][0] = sm.g.As[r0][ks + tg];
                    afr[mt][1] = sm.g.As[r0 + 8][ks + tg];
                    afr[mt][2] = sm.g.As[r0][ks + tg + 4];
                    afr[mt][3] = sm.g.As[r0 + 8][ks + tg + 4];
                }
                #pragma unroll
                for (int nt = 0; nt < 4; nt++) {
                    int r0 = wn + nt * 8 + g;
                    bfr[nt][0] = sm.g.Bs[r0][ks + tg];
                    bfr[nt][1] = sm.g.Bs[r0][ks + tg + 4];
                }
                #pragma unroll
                for (int mt = 0; mt < 2; mt++)
                    #pragma unroll
                    for (int nt = 0; nt < 4; nt++)
                        mma_tf32(c[mt][nt], afr[mt], bfr[nt]);
            }
        }
        // epilogue: write gh
        #pragma unroll
        for (int mt = 0; mt < 2; mt++) {
            int row = m0 + wm + mt * 16 + g;
            #pragma unroll
            for (int nt = 0; nt < 4; nt++) {
                int col = n0 + wn + nt * 8 + 2 * tg;
                *(float2*)(g_gh + (size_t)row * (3 * H_DIM) + col)
                    = make_float2(c[mt][nt][0], c[mt][nt][1]);
                *(float2*)(g_gh + (size_t)(row + 8) * (3 * H_DIM) + col)
                    = make_float2(c[mt][nt][2], c[mt][nt][3]);
            }
        }
    } else {
        // ---- gather path: hkp += beta_j * alpha_kk * hs[idx_j, kk, :] ----
        int g = blockIdx.x - GEMM_BLOCKS;       // 0..511
        int j = g & 63;
        int kk0 = (g >> 6) * 128;
        if (tid < 128) sm.t.sal[tid] = g_alpha[kk0 + tid];
        __syncthreads();

        int slice = g_topidx[j];
        const float4* base = (const float4*)hs
                           + (size_t)slice * (K_LEN * (H_DIM / 4))
                           + (size_t)kk0 * (H_DIM / 4);
        int t4 = tid & 63;
        int rg = tid >> 6;
        float4 acc = make_float4(0.f, 0.f, 0.f, 0.f);
        #pragma unroll 8
        for (int r = rg; r < 128; r += 4) {
            float a = sm.t.sal[r];
            float4 vv = base[r * (H_DIM / 4) + t4];
            acc.x += a * vv.x; acc.y += a * vv.y;
            acc.z += a * vv.z; acc.w += a * vv.w;
        }
        sm.t.sacc[tid] = acc;
        __syncthreads();
        if (tid < 64) {
            float4 a0 = sm.t.sacc[tid], a1 = sm.t.sacc[64 + tid];
            float4 a2 = sm.t.sacc[128 + tid], a3 = sm.t.sacc[192 + tid];
            float b = g_beta[j];
            atomicAdd(&g_hkp[tid * 4 + 0], b * (a0.x + a1.x + a2.x + a3.x));
            atomicAdd(&g_hkp[tid * 4 + 1], b * (a0.y + a1.y + a2.y + a3.y));
            atomicAdd(&g_hkp[tid * 4 + 2], b * (a0.z + a1.z + a2.z + a3.z));
            atomicAdd(&g_hkp[tid * 4 + 3], b * (a0.w + a1.w + a2.w + a3.w));
        }
    }
}

// ---------------- K5: GRU gates + h_new + predict_score ------------------
__global__ void k5_gru(const float* __restrict__ h0,
                       const float* __restrict__ b_ih,
                       const float* __restrict__ b_hh,
                       const float* __restrict__ W_score,
                       const float* __restrict__ b_score,
                       float* __restrict__ out) {
    int kk = blockIdx.x;
    int hh = threadIdx.x;
    float a = g_alpha[kk];
    const float* gh = g_gh + (size_t)kk * (3 * H_DIM);

    float gir = fmaf(a, g_u[hh],             b_ih[hh]);
    float giz = fmaf(a, g_u[H_DIM + hh],     b_ih[H_DIM + hh]);
    float gin = fmaf(a, g_u[2 * H_DIM + hh], b_ih[2 * H_DIM + hh]);
    float ghr = gh[hh]             + b_hh[hh];
    float ghz = gh[H_DIM + hh]     + b_hh[H_DIM + hh];
    float ghn = gh[2 * H_DIM + hh] + b_hh[2 * H_DIM + hh];

    float r = 1.f / (1.f + __expf(-(gir + ghr)));
    float z = 1.f / (1.f + __expf(-(giz + ghz)));
    float n = tanhf(gin + r * ghn);
    float h0v = h0[(size_t)kk * H_DIM + hh];
    out[1 + (size_t)kk * H_DIM + hh] = (1.f - z) * n + z * h0v;

    if (kk == 0 && hh < 32) {
        float p = 0.f;
        for (int i = hh; i < TOPIC + H_DIM; i += 32) {
            float pv = (i < TOPIC) ? g_v[i] : g_hkp[i - TOPIC];
            p += W_score[i] * pv;
        }
        #pragma unroll
        for (int o = 16; o; o >>= 1) p += __shfl_xor_sync(0xffffffffu, p, o);
        if (hh == 0) out[0] = p + b_score[0];
    }
}

// ---------------------------------------------------------------------------
extern "C" void kernel_launch(void* const* d_in, const int* in_sizes, int n_in,
                              void* d_out, int out_size) {
    const float* co_e     = (const float*)d_in[0];
    const float* ex_e     = (const float*)d_in[1];
    const float* s        = (const float*)d_in[2];
    const float* h        = (const float*)d_in[3];
    const float* vs       = (const float*)d_in[4];
    const float* hs       = (const float*)d_in[5];
    const float* W_resize = (const float*)d_in[6];
    const float* b_resize = (const float*)d_in[7];
    const float* Wk       = (const float*)d_in[8];
    const float* bk       = (const float*)d_in[9];
    const float* km       = (const float*)d_in[10];
    const float* W_score  = (const float*)d_in[11];
    const float* b_score  = (const float*)d_in[12];
    const float* W_ih     = (const float*)d_in[13];
    const float* W_hh     = (const float*)d_in[14];
    const float* b_ih     = (const float*)d_in[15];
    const float* b_hh     = (const float*)d_in[16];
    float* out = (float*)d_out;

    k1_embed<<<21, 256>>>(W_resize, b_resize, ex_e, Wk, bk, co_e);
    k2_dots <<<352, 256>>>(vs, km, W_ih, s);
    k3_select<<<1, 1024>>>();
    k4_fused<<<GEMM_BLOCKS + 512, 256>>>(h, W_hh, hs);
    k5_gru  <<<K_LEN, 256>>>(h, b_ih, b_hh, W_score, b_score, out);
}